// round 1
// baseline (speedup 1.0000x reference)
#include <cuda_runtime.h>
#include <math.h>

// Batched sym_logm of 8192 SPD 64x64 fp32 matrices.
// One CTA per matrix. Cyclic Jacobi eigensolver with round-robin parallel
// ordering (32 disjoint pairs/round, 63 rounds/sweep), then V*diag(log w)*V^T.

#define Nn 64
#define NP 65            // padded row stride (odd -> conflict-free column access)
#define TPB 256
#define MAX_SWEEPS 16

// Round-robin tournament pairing for round r (0..62), pair i (0..31).
// i==0: (63, r). else: ((r+i) mod 63, (r-i) mod 63). Covers all pairs over 63 rounds.
__device__ __forceinline__ void pair_of(int r, int i, int& p, int& q) {
    if (i == 0) { p = 63; q = r; }
    else {
        p = r + i;      if (p >= 63) p -= 63;
        q = r - i;      if (q < 0)   q += 63;
    }
}

__global__ __launch_bounds__(TPB) void logeig_kernel(const float* __restrict__ X,
                                                     float* __restrict__ out)
{
    __shared__ float A[Nn * NP];   // working symmetric matrix
    __shared__ float V[Nn * NP];   // accumulated eigenvectors (columns)
    __shared__ float cs[32], ss[32];
    __shared__ float red[TPB];
    __shared__ float ld[Nn];

    const int b   = blockIdx.x;
    const int tid = threadIdx.x;
    const float* Xb = X + (size_t)b * (Nn * Nn);

    // ---- Load A, init V = I, accumulate ||A||_F^2 ----
    float fr = 0.0f;
    for (int idx = tid; idx < Nn * Nn; idx += TPB) {
        int i = idx >> 6, j = idx & 63;
        float v = Xb[idx];
        A[i * NP + j] = v;
        V[i * NP + j] = (i == j) ? 1.0f : 0.0f;
        fr += v * v;
    }
    red[tid] = fr;
    __syncthreads();
    for (int ofs = TPB / 2; ofs > 0; ofs >>= 1) {
        if (tid < ofs) red[tid] += red[tid + ofs];
        __syncthreads();
    }
    const float fro2 = red[0];
    __syncthreads();

    // ---- Jacobi sweeps ----
    for (int sweep = 0; sweep < MAX_SWEEPS; ++sweep) {
        for (int r = 0; r < 63; ++r) {
            // 1) rotation angles for the 32 disjoint pairs
            if (tid < 32) {
                int p, q; pair_of(r, tid, p, q);
                float app = A[p * NP + p];
                float aqq = A[q * NP + q];
                float apq = A[p * NP + q];
                float c = 1.0f, s = 0.0f;
                if (fabsf(apq) > 1e-9f * (fabsf(app) + fabsf(aqq))) {
                    float theta = 0.5f * (aqq - app) / apq;      // cot(2*phi)
                    float t = copysignf(1.0f, theta) /
                              (fabsf(theta) + sqrtf(theta * theta + 1.0f));
                    c = rsqrtf(1.0f + t * t);
                    s = t * c;
                }
                cs[tid] = c; ss[tid] = s;
            }
            __syncthreads();

            // 2) row phase: A <- G^T A   (rows p,q rotated; pairs disjoint)
            #pragma unroll
            for (int u = tid; u < 2048; u += TPB) {
                int i = u >> 6, k = u & 63;
                float s = ss[i];
                if (s != 0.0f) {
                    float c = cs[i];
                    int p, q; pair_of(r, i, p, q);
                    float ap = A[p * NP + k];
                    float aq = A[q * NP + k];
                    A[p * NP + k] = c * ap - s * aq;
                    A[q * NP + k] = s * ap + c * aq;
                }
            }
            __syncthreads();

            // 3) col phase: A <- A G; and V <- V G
            #pragma unroll
            for (int u = tid; u < 2048; u += TPB) {
                int i = u >> 6, k = u & 63;
                float s = ss[i];
                if (s != 0.0f) {
                    float c = cs[i];
                    int p, q; pair_of(r, i, p, q);
                    float ap = A[k * NP + p];
                    float aq = A[k * NP + q];
                    A[k * NP + p] = c * ap - s * aq;
                    A[k * NP + q] = s * ap + c * aq;
                    float vp = V[k * NP + p];
                    float vq = V[k * NP + q];
                    V[k * NP + p] = c * vp - s * vq;
                    V[k * NP + q] = s * vp + c * vq;
                }
            }
            __syncthreads();
        }

        // convergence check: off-diagonal Frobenius^2 vs initial ||A||_F^2
        float off = 0.0f;
        for (int idx = tid; idx < Nn * Nn; idx += TPB) {
            int i = idx >> 6, j = idx & 63;
            if (i != j) { float a = A[i * NP + j]; off += a * a; }
        }
        red[tid] = off;
        __syncthreads();
        for (int ofs = TPB / 2; ofs > 0; ofs >>= 1) {
            if (tid < ofs) red[tid] += red[tid + ofs];
            __syncthreads();
        }
        if (red[0] <= 1e-12f * fro2) break;   // uniform across CTA
        __syncthreads();
    }

    // ---- log of eigenvalues (diagonal of converged A) ----
    if (tid < Nn) ld[tid] = logf(fmaxf(A[tid * NP + tid], 1e-38f));
    __syncthreads();

    // ---- W = V * diag(log w), stored into A ----
    for (int idx = tid; idx < Nn * Nn; idx += TPB) {
        int i = idx >> 6, k = idx & 63;
        A[i * NP + k] = V[i * NP + k] * ld[k];
    }
    __syncthreads();

    // ---- out[i][j] = sum_k W[i][k] * V[j][k] ----
    float* Ob = out + (size_t)b * (Nn * Nn);
    for (int idx = tid; idx < Nn * Nn; idx += TPB) {
        int i = idx >> 6, j = idx & 63;
        float acc = 0.0f;
        #pragma unroll 16
        for (int k = 0; k < Nn; ++k)
            acc += A[i * NP + k] * V[j * NP + k];
        Ob[idx] = acc;
    }
}

extern "C" void kernel_launch(void* const* d_in, const int* in_sizes, int n_in,
                              void* d_out, int out_size) {
    const float* X = (const float*)d_in[0];
    float* out = (float*)d_out;
    int B = in_sizes[0] / (Nn * Nn);
    logeig_kernel<<<B, TPB>>>(X, out);
}

// round 2
// speedup vs baseline: 2.2975x; 2.2975x over previous
#include <cuda_runtime.h>
#include <math.h>

// sym_logm of B SPD 64x64 fp32 matrices.
// Kernel 1: one-sided Hestenes Jacobi, ONE WARP per matrix, both owned
//           columns fully register-resident. Brent-Luk tournament re-pairing
//           via warp shuffles. Writes G and W = G * diag(log(l)/l^2) to scratch.
// Kernel 2: batched out = G_cols^T-style product: out[i][j] = sum_k P[k][i]*Q[k][j].

#define MAXB 8192
#define NMAT 64

__device__ float g_P[(size_t)MAXB * NMAT * NMAT];
__device__ float g_Q[(size_t)MAXB * NMAT * NMAT];

__global__ __launch_bounds__(128) void jacobi_onesided(const float* __restrict__ X, int B)
{
    const int warp = blockIdx.x * (blockDim.x >> 5) + (threadIdx.x >> 5);
    if (warp >= B) return;
    const int lane = threadIdx.x & 31;
    const unsigned FULL = 0xffffffffu;

    // Each lane owns two columns of G (initially columns lane and lane+32 of X).
    // X is symmetric, so column c == row c -> coalesced-ish float4 row loads.
    const float4* x4 = (const float4*)(X + (size_t)warp * (NMAT * NMAT));
    float ca[64], cb[64];
    #pragma unroll
    for (int r = 0; r < 16; ++r) {
        float4 v = x4[lane * 16 + r];
        ca[4*r+0] = v.x; ca[4*r+1] = v.y; ca[4*r+2] = v.z; ca[4*r+3] = v.w;
        float4 w = x4[(lane + 32) * 16 + r];
        cb[4*r+0] = w.x; cb[4*r+1] = w.y; cb[4*r+2] = w.z; cb[4*r+3] = w.w;
    }

    // Carried Gram diagonals (squared column norms; for SPD these -> lambda^2).
    float app = 0.0f, abb = 0.0f;
    #pragma unroll
    for (int k = 0; k < 64; ++k) {
        app = fmaf(ca[k], ca[k], app);
        abb = fmaf(cb[k], cb[k], abb);
    }

    for (int sweep = 0; sweep < 30; ++sweep) {
        int any = 0;
        for (int r = 0; r < 63; ++r) {
            // apq = <ca, cb> with 4-way ILP
            float d0 = 0.f, d1 = 0.f, d2 = 0.f, d3 = 0.f;
            #pragma unroll
            for (int k = 0; k < 64; k += 4) {
                d0 = fmaf(ca[k+0], cb[k+0], d0);
                d1 = fmaf(ca[k+1], cb[k+1], d1);
                d2 = fmaf(ca[k+2], cb[k+2], d2);
                d3 = fmaf(ca[k+3], cb[k+3], d3);
            }
            float apq = (d0 + d1) + (d2 + d3);

            // rotate iff |apq| > 3e-7 * sqrt(app*abb)
            bool rot = (apq * apq > 9e-14f * app * abb);
            if (rot) {
                float th = 0.5f * (abb - app) / apq;
                float t  = copysignf(1.0f, th) / (fabsf(th) + sqrtf(fmaf(th, th, 1.0f)));
                float cc = rsqrtf(fmaf(t, t, 1.0f));
                float ss = t * cc;
                #pragma unroll
                for (int k = 0; k < 64; ++k) {
                    float x = ca[k], y = cb[k];
                    ca[k] = fmaf(cc, x, -ss * y);
                    cb[k] = fmaf(ss, x,  cc * y);
                }
                app = fmaf(-t, apq, app);
                abb = fmaf( t, apq, abb);
                any = 1;
            }

            // Brent-Luk re-pairing (t0 fixed):
            //   t1 <- b0 ; t_i <- t_{i-1} (i>=2) ; b_i <- b_{i+1} (i<=30) ; b31 <- t31
            #pragma unroll
            for (int k = 0; k < 64; ++k) {
                float outv = (lane == 0) ? cb[k] : ca[k];
                float nt = __shfl_up_sync(FULL, outv, 1);
                float nb = __shfl_down_sync(FULL, cb[k], 1);
                float oldt = ca[k];
                if (lane != 0) ca[k] = nt;
                cb[k] = (lane == 31) ? oldt : nb;
            }
            {   // norms travel with their columns
                float outv = (lane == 0) ? abb : app;
                float nt = __shfl_up_sync(FULL, outv, 1);
                float nb = __shfl_down_sync(FULL, abb, 1);
                float oldt = app;
                if (lane != 0) app = nt;
                abb = (lane == 31) ? oldt : nb;
            }
        }
        if (!__any_sync(FULL, any)) break;
    }

    // Recompute exact norms (kills analytic-carry drift), then weights.
    float na = 0.0f, nb2 = 0.0f;
    #pragma unroll
    for (int k = 0; k < 64; ++k) {
        na  = fmaf(ca[k], ca[k], na);
        nb2 = fmaf(cb[k], cb[k], nb2);
    }
    // column norm^2 = lambda^2 ; weight w = log(lambda)/lambda^2 = 0.5*log(na)/na
    float wa = 0.5f * logf(fmaxf(na,  1e-30f)) / na;
    float wb = 0.5f * logf(fmaxf(nb2, 1e-30f)) / nb2;

    // Store P = G columns, Q = w * G columns. Layout: [b][col][row], rows contiguous.
    float4* Pp = (float4*)(g_P + (size_t)warp * (NMAT * NMAT));
    float4* Qp = (float4*)(g_Q + (size_t)warp * (NMAT * NMAT));
    #pragma unroll
    for (int r = 0; r < 16; ++r) {
        Pp[lane * 16 + r] = make_float4(ca[4*r], ca[4*r+1], ca[4*r+2], ca[4*r+3]);
        Qp[lane * 16 + r] = make_float4(wa*ca[4*r], wa*ca[4*r+1], wa*ca[4*r+2], wa*ca[4*r+3]);
        Pp[(lane + 32) * 16 + r] = make_float4(cb[4*r], cb[4*r+1], cb[4*r+2], cb[4*r+3]);
        Qp[(lane + 32) * 16 + r] = make_float4(wb*cb[4*r], wb*cb[4*r+1], wb*cb[4*r+2], wb*cb[4*r+3]);
    }
}

// out[b][i][j] = sum_k P[b][k][i] * Q[b][k][j]
__global__ __launch_bounds__(256) void gram_epilogue(float* __restrict__ out, int B)
{
    __shared__ float Ps[NMAT * NMAT];
    __shared__ float Qs[NMAT * NMAT];
    const int b = blockIdx.x;
    const int tid = threadIdx.x;
    const float* Pb = g_P + (size_t)b * (NMAT * NMAT);
    const float* Qb = g_Q + (size_t)b * (NMAT * NMAT);

    #pragma unroll
    for (int i = tid; i < NMAT * NMAT; i += 256) {
        Ps[i] = Pb[i];
        Qs[i] = Qb[i];
    }
    __syncthreads();

    const int ti = tid >> 6;       // 0..3 -> rows [16*ti, 16*ti+16)
    const int tj = tid & 63;       // output column
    float acc[16];
    #pragma unroll
    for (int r = 0; r < 16; ++r) acc[r] = 0.0f;

    #pragma unroll 4
    for (int k = 0; k < NMAT; ++k) {
        float qv = Qs[k * NMAT + tj];
        const float4* prow = (const float4*)&Ps[k * NMAT + ti * 16];
        #pragma unroll
        for (int r4 = 0; r4 < 4; ++r4) {
            float4 p = prow[r4];
            acc[4*r4+0] = fmaf(p.x, qv, acc[4*r4+0]);
            acc[4*r4+1] = fmaf(p.y, qv, acc[4*r4+1]);
            acc[4*r4+2] = fmaf(p.z, qv, acc[4*r4+2]);
            acc[4*r4+3] = fmaf(p.w, qv, acc[4*r4+3]);
        }
    }

    float* Ob = out + (size_t)b * (NMAT * NMAT);
    #pragma unroll
    for (int r = 0; r < 16; ++r)
        Ob[(ti * 16 + r) * NMAT + tj] = acc[r];
}

extern "C" void kernel_launch(void* const* d_in, const int* in_sizes, int n_in,
                              void* d_out, int out_size) {
    const float* X = (const float*)d_in[0];
    float* out = (float*)d_out;
    int B = in_sizes[0] / (NMAT * NMAT);
    if (B > MAXB) B = MAXB;
    int warps_per_block = 4;
    int blocks = (B + warps_per_block - 1) / warps_per_block;
    jacobi_onesided<<<blocks, warps_per_block * 32>>>(X, B);
    gram_epilogue<<<B, 256>>>(out, B);
}